// round 2
// baseline (speedup 1.0000x reference)
#include <cuda_runtime.h>
#include <cuda_bf16.h>
#include <math.h>

// Problem constants (fixed shapes for Contrast_69380901699721)
#define BATCH 4096
#define DIM   512
#define NTOT  8192            // 2*BATCH
#define INV_TEMP 2.0f         // 1/0.5

// Tiling for the fused similarity kernel
#define BM 64
#define BN 64
#define BK 16
#define PAD 4

// Scratch (no cudaMalloc allowed) — 16 MB for normalized Z + per-row loss
__device__ float g_z[NTOT * DIM];
__device__ float g_rowloss[NTOT];

// ---------------------------------------------------------------------------
// Kernel 1: L2-normalize rows of x_i / x_j into concatenated Z (8192 x 512)
// One block (128 threads) per row; each thread handles one float4.
// ---------------------------------------------------------------------------
__global__ __launch_bounds__(128) void norm_kernel(const float* __restrict__ xi,
                                                   const float* __restrict__ xj) {
    const int row = blockIdx.x;                       // 0..8191
    const float* src = (row < BATCH) ? (xi + (size_t)row * DIM)
                                     : (xj + (size_t)(row - BATCH) * DIM);
    float4 v = ((const float4*)src)[threadIdx.x];     // 128 threads * 4 = 512
    float ss = v.x * v.x + v.y * v.y + v.z * v.z + v.w * v.w;

    // warp reduce
    #pragma unroll
    for (int o = 16; o > 0; o >>= 1) ss += __shfl_xor_sync(0xFFFFFFFFu, ss, o);

    __shared__ float ws[4];
    if ((threadIdx.x & 31) == 0) ws[threadIdx.x >> 5] = ss;
    __syncthreads();
    float tot = ws[0] + ws[1] + ws[2] + ws[3];

    // matches F.normalize: x / max(||x||, eps)
    float inv = 1.0f / fmaxf(sqrtf(tot), 1e-12f);
    float4 o4 = make_float4(v.x * inv, v.y * inv, v.z * inv, v.w * inv);
    ((float4*)(g_z + (size_t)row * DIM))[threadIdx.x] = o4;
}

// ---------------------------------------------------------------------------
// Kernel 2: fused sim = Z Z^T tile GEMM + exp/row-sum epilogue.
// Grid: NTOT/BM blocks. Each block owns BM rows, loops over all NTOT columns.
// 256 threads as 16x16; each thread computes a 4x4 micro-tile.
// Per row r: denom_r = sum_{c != r} exp(2*sim[r,c]),  pos_r = sim[r, r (+/-) B]
// writes rowloss[r] = log(denom_r) - 2*pos_r
// ---------------------------------------------------------------------------
__global__ __launch_bounds__(256) void sim_kernel(float* __restrict__ rowloss) {
    __shared__ float As[BK][BM + PAD];
    __shared__ float Bs[BK][BN + PAD];
    __shared__ float red[BM][17];

    const int tid = threadIdx.x;
    const int tx = tid & 15;       // 0..15 -> columns
    const int ty = tid >> 4;       // 0..15 -> rows
    const int rowBase = blockIdx.x * BM;

    // cooperative load mapping: thread -> (row-in-tile, k-offset), one float4 each
    const int lr = tid >> 2;            // 0..63
    const int lk = (tid & 3) * 4;       // 0,4,8,12

    float rowsum[4] = {0.f, 0.f, 0.f, 0.f};
    float posv[4]   = {0.f, 0.f, 0.f, 0.f};

    const float* __restrict__ z = g_z;

    for (int colBase = 0; colBase < NTOT; colBase += BN) {
        float acc[4][4];
        #pragma unroll
        for (int i = 0; i < 4; i++)
            #pragma unroll
            for (int j = 0; j < 4; j++) acc[i][j] = 0.f;

        for (int kk = 0; kk < DIM; kk += BK) {
            float4 av = *(const float4*)(z + (size_t)(rowBase + lr) * DIM + kk + lk);
            float4 bv = *(const float4*)(z + (size_t)(colBase + lr) * DIM + kk + lk);
            As[lk + 0][lr] = av.x; As[lk + 1][lr] = av.y;
            As[lk + 2][lr] = av.z; As[lk + 3][lr] = av.w;
            Bs[lk + 0][lr] = bv.x; Bs[lk + 1][lr] = bv.y;
            Bs[lk + 2][lr] = bv.z; Bs[lk + 3][lr] = bv.w;
            __syncthreads();

            #pragma unroll
            for (int k = 0; k < BK; k++) {
                float4 a = *(const float4*)&As[k][ty * 4];
                float4 b = *(const float4*)&Bs[k][tx * 4];
                acc[0][0] += a.x * b.x; acc[0][1] += a.x * b.y;
                acc[0][2] += a.x * b.z; acc[0][3] += a.x * b.w;
                acc[1][0] += a.y * b.x; acc[1][1] += a.y * b.y;
                acc[1][2] += a.y * b.z; acc[1][3] += a.y * b.w;
                acc[2][0] += a.z * b.x; acc[2][1] += a.z * b.y;
                acc[2][2] += a.z * b.z; acc[2][3] += a.z * b.w;
                acc[3][0] += a.w * b.x; acc[3][1] += a.w * b.y;
                acc[3][2] += a.w * b.z; acc[3][3] += a.w * b.w;
            }
            __syncthreads();
        }

        // fused epilogue: exp + masked row-sum + positive capture
        #pragma unroll
        for (int i = 0; i < 4; i++) {
            const int gr = rowBase + ty * 4 + i;
            const int partner = (gr < BATCH) ? gr + BATCH : gr - BATCH;
            #pragma unroll
            for (int j = 0; j < 4; j++) {
                const int gc = colBase + tx * 4 + j;
                const float s = acc[i][j];
                const float e = __expf(INV_TEMP * s);
                if (gc != gr)      rowsum[i] += e;   // mask diagonal
                if (gc == partner) posv[i]    = s;   // positive pair sim
            }
        }
    }

    // cross-thread reduction over the 16 column-thread groups per row
    #pragma unroll
    for (int i = 0; i < 4; i++) red[ty * 4 + i][tx] = rowsum[i];
    __syncthreads();
    float denom = 0.f;
    if (tid < BM) {
        #pragma unroll
        for (int t = 0; t < 16; t++) denom += red[tid][t];
    }
    __syncthreads();
    #pragma unroll
    for (int i = 0; i < 4; i++) red[ty * 4 + i][tx] = posv[i];
    __syncthreads();
    if (tid < BM) {
        float p = 0.f;
        #pragma unroll
        for (int t = 0; t < 16; t++) p += red[tid][t];  // exactly one nonzero
        rowloss[rowBase + tid] = logf(denom) - INV_TEMP * p;
    }
}

// ---------------------------------------------------------------------------
// Kernel 3: mean over 8192 row losses -> scalar
// ---------------------------------------------------------------------------
__global__ __launch_bounds__(256) void reduce_kernel(const float* __restrict__ rowloss,
                                                     float* __restrict__ out) {
    __shared__ float s[256];
    float v = 0.f;
    for (int i = threadIdx.x; i < NTOT; i += 256) v += rowloss[i];
    s[threadIdx.x] = v;
    __syncthreads();
    for (int stride = 128; stride > 0; stride >>= 1) {
        if (threadIdx.x < stride) s[threadIdx.x] += s[threadIdx.x + stride];
        __syncthreads();
    }
    if (threadIdx.x == 0) out[0] = s[0] * (1.0f / (float)NTOT);
}

// ---------------------------------------------------------------------------
extern "C" void kernel_launch(void* const* d_in, const int* in_sizes, int n_in,
                              void* d_out, int out_size) {
    const float* x_i = (const float*)d_in[0];
    const float* x_j = (const float*)d_in[1];
    float* out = (float*)d_out;

    float* z_ptr;
    float* rowloss_ptr;
    cudaGetSymbolAddress((void**)&z_ptr, g_z);
    cudaGetSymbolAddress((void**)&rowloss_ptr, g_rowloss);

    norm_kernel<<<NTOT, 128>>>(x_i, x_j);
    sim_kernel<<<NTOT / BM, 256>>>(rowloss_ptr);
    reduce_kernel<<<1, 256>>>(rowloss_ptr, out);
}

// round 4
// speedup vs baseline: 17.0693x; 17.0693x over previous
#include <cuda_runtime.h>
#include <cuda_bf16.h>
#include <math.h>
#include <stdint.h>

// Problem constants
#define BATCH 4096
#define DIM   512
#define NTOT  8192
#define TILE  128
#define KCHUNK 64
#define NCHUNKS (DIM / KCHUNK)   // 8

// SMEM: double-buffered A and B tiles, each 128 rows x 64 bf16 = 16 KB
#define TILE_BYTES 16384
#define SM_A(buf) ((buf) * TILE_BYTES)
#define SM_B(buf) (2 * TILE_BYTES + (buf) * TILE_BYTES)
#define SM_TOTAL  (4 * TILE_BYTES)

// Scratch (no cudaMalloc allowed)
__device__ __nv_bfloat16 g_zb[NTOT * DIM];   // normalized Z, bf16 (8 MB)
__device__ float g_denom[NTOT];
__device__ float g_pos[NTOT];

// ---------------------------------------------------------------------------
__device__ __forceinline__ uint32_t smem_u32(const void* p) {
    uint32_t a;
    asm("{ .reg .u64 t; cvta.to.shared.u64 t, %1; cvt.u32.u64 %0, t; }" : "=r"(a) : "l"(p));
    return a;
}

__device__ __forceinline__ void cp_async16(uint32_t saddr, const void* gptr) {
    asm volatile("cp.async.cg.shared.global [%0], [%1], 16;" :: "r"(saddr), "l"(gptr));
}
__device__ __forceinline__ void cp_commit() {
    asm volatile("cp.async.commit_group;" ::: "memory");
}
template <int N>
__device__ __forceinline__ void cp_wait() {
    asm volatile("cp.async.wait_group %0;" :: "n"(N) : "memory");
}

__device__ __forceinline__ void ldsm_x4(uint32_t* r, uint32_t addr) {
    asm volatile("ldmatrix.sync.aligned.m8n8.x4.shared.b16 {%0,%1,%2,%3}, [%4];"
                 : "=r"(r[0]), "=r"(r[1]), "=r"(r[2]), "=r"(r[3]) : "r"(addr));
}

__device__ __forceinline__ void mma16816(float* c, const uint32_t* a, const uint32_t* b) {
    asm volatile(
        "mma.sync.aligned.m16n8k16.row.col.f32.bf16.bf16.f32 "
        "{%0,%1,%2,%3}, {%4,%5,%6,%7}, {%8,%9}, {%0,%1,%2,%3};"
        : "+f"(c[0]), "+f"(c[1]), "+f"(c[2]), "+f"(c[3])
        : "r"(a[0]), "r"(a[1]), "r"(a[2]), "r"(a[3]), "r"(b[0]), "r"(b[1]));
}

// Fast exp(2*s) on the FMA pipe (avoid MUFU.EX2 throughput wall).
__device__ __forceinline__ float fast_exp2s(float s) {
    float t = 2.8853900817779268f * s;      // 2 * log2(e)
    float fn = rintf(t);
    float f = t - fn;
    float p = fmaf(0.0013333558f, f, 0.0096181291f);
    p = fmaf(p, f, 0.0555041087f);
    p = fmaf(p, f, 0.2402265070f);
    p = fmaf(p, f, 0.6931471806f);
    p = fmaf(p, f, 1.0f);
    int n = (int)fn;
    float scale = __int_as_float((n + 127) << 23);
    return p * scale;
}

// ---------------------------------------------------------------------------
// Kernel 1: L2-normalize rows into bf16 Z; zero accumulators.
// ---------------------------------------------------------------------------
__global__ __launch_bounds__(128) void norm_kernel(const float* __restrict__ xi,
                                                   const float* __restrict__ xj) {
    const int row = blockIdx.x;
    const float* src = (row < BATCH) ? (xi + (size_t)row * DIM)
                                     : (xj + (size_t)(row - BATCH) * DIM);
    float4 v = ((const float4*)src)[threadIdx.x];
    float ss = v.x * v.x + v.y * v.y + v.z * v.z + v.w * v.w;
    #pragma unroll
    for (int o = 16; o > 0; o >>= 1) ss += __shfl_xor_sync(0xFFFFFFFFu, ss, o);
    __shared__ float ws[4];
    if ((threadIdx.x & 31) == 0) ws[threadIdx.x >> 5] = ss;
    __syncthreads();
    float tot = ws[0] + ws[1] + ws[2] + ws[3];
    float inv = 1.0f / fmaxf(sqrtf(tot), 1e-12f);

    __nv_bfloat162 h0 = __floats2bfloat162_rn(v.x * inv, v.y * inv);
    __nv_bfloat162 h1 = __floats2bfloat162_rn(v.z * inv, v.w * inv);
    uint2 u;
    u.x = *(uint32_t*)&h0;
    u.y = *(uint32_t*)&h1;
    ((uint2*)(g_zb + (size_t)row * DIM))[threadIdx.x] = u;

    if (threadIdx.x == 0) {
        g_denom[row] = 0.0f;
        g_pos[row] = 0.0f;
    }
}

// ---------------------------------------------------------------------------
// Kernel 2: 128x128 sim tile per CTA via bf16 mma.sync (HMMA.16816),
// cp.async double-buffered mainloop, register-fused exp/rowsum epilogue.
// Grid (64, 64), 256 threads = 8 warps (4 m-strips x 2 n-strips).
// ---------------------------------------------------------------------------
__global__ __launch_bounds__(256, 2) void sim_kernel() {
    extern __shared__ char smem[];
    const uint32_t sbase = smem_u32(smem);
    const int tid = threadIdx.x;
    const int wid = tid >> 5;
    const int lane = tid & 31;

    const int rowBase = blockIdx.y * TILE;
    const int colBase = blockIdx.x * TILE;

    const int warp_m = wid & 3;     // 0..3 -> 32-row strip
    const int warp_n = wid >> 2;    // 0..1 -> 64-col strip

    const __nv_bfloat16* __restrict__ zb = g_zb;

    // --- cp.async load mapping: 1024 16B units per tile, 4 per thread ---
    // idx = tid + it*256 ; r = idx>>3 ; c16 = idx&7
    // swizzled smem byte off = r*128 + (c16*16 ^ ((r&7)<<4))
    uint32_t ld_soff[4];
    const __nv_bfloat16* ld_ga[4];
    const __nv_bfloat16* ld_gb[4];
    #pragma unroll
    for (int it = 0; it < 4; it++) {
        int idx = tid + it * 256;
        int r = idx >> 3;
        int c16 = idx & 7;
        ld_soff[it] = (uint32_t)(r * 128 + ((c16 * 16) ^ ((r & 7) << 4)));
        ld_ga[it] = zb + (size_t)(rowBase + r) * DIM + c16 * 8;
        ld_gb[it] = zb + (size_t)(colBase + r) * DIM + c16 * 8;
    }

    // --- ldmatrix address components (swizzle folded into col xor) ---
    // A: row_in_tile = warp_m*32 + mt*16 + (lane&15); col byte = kt*32 + (lane>>4)*16
    // B: per nt-pair p: q=lane>>3; n_row = warp_n*64 + (2p + (q>>1))*8 + (lane&7);
    //    col byte = kt*32 + (q&1)*16
    uint32_t aRow[2], aMask[2];
    #pragma unroll
    for (int mt = 0; mt < 2; mt++) {
        int r = warp_m * 32 + mt * 16 + (lane & 15);
        aRow[mt] = (uint32_t)(r * 128);
        aMask[mt] = (uint32_t)((r & 7) << 4);
    }
    const uint32_t aColK = (uint32_t)((lane >> 4) * 16);

    uint32_t bRow[4], bMask[4];
    const int q = lane >> 3;
    #pragma unroll
    for (int p = 0; p < 4; p++) {
        int r = warp_n * 64 + (2 * p + (q >> 1)) * 8 + (lane & 7);
        bRow[p] = (uint32_t)(r * 128);
        bMask[p] = (uint32_t)((r & 7) << 4);
    }
    const uint32_t bColK = (uint32_t)((q & 1) * 16);

    float acc[2][8][4];
    #pragma unroll
    for (int mt = 0; mt < 2; mt++)
        #pragma unroll
        for (int nt = 0; nt < 8; nt++)
            #pragma unroll
            for (int k = 0; k < 4; k++) acc[mt][nt][k] = 0.0f;

    // --- prologue: load chunk 0 into buffer 0 ---
    #pragma unroll
    for (int it = 0; it < 4; it++) {
        cp_async16(sbase + SM_A(0) + ld_soff[it], ld_ga[it]);
        cp_async16(sbase + SM_B(0) + ld_soff[it], ld_gb[it]);
    }
    cp_commit();

    for (int kk = 0; kk < NCHUNKS; kk++) {
        const int buf = kk & 1;
        if (kk + 1 < NCHUNKS) {
            const int nb = (kk + 1) & 1;
            const int koff = (kk + 1) * KCHUNK;
            #pragma unroll
            for (int it = 0; it < 4; it++) {
                cp_async16(sbase + SM_A(nb) + ld_soff[it], ld_ga[it] + koff);
                cp_async16(sbase + SM_B(nb) + ld_soff[it], ld_gb[it] + koff);
            }
            cp_commit();
            cp_wait<1>();
        } else {
            cp_wait<0>();
        }
        __syncthreads();

        const uint32_t abase = sbase + SM_A(buf);
        const uint32_t bbase = sbase + SM_B(buf);

        #pragma unroll
        for (int kt = 0; kt < 4; kt++) {
            const uint32_t kb = (uint32_t)(kt * 32);
            uint32_t a[2][4];
            #pragma unroll
            for (int mt = 0; mt < 2; mt++)
                ldsm_x4(a[mt], abase + aRow[mt] + ((kb + aColK) ^ aMask[mt]));

            uint32_t b[8][2];
            #pragma unroll
            for (int p = 0; p < 4; p++) {
                uint32_t r4[4];
                ldsm_x4(r4, bbase + bRow[p] + ((kb + bColK) ^ bMask[p]));
                b[2 * p][0] = r4[0]; b[2 * p][1] = r4[1];
                b[2 * p + 1][0] = r4[2]; b[2 * p + 1][1] = r4[3];
            }

            #pragma unroll
            for (int mt = 0; mt < 2; mt++)
                #pragma unroll
                for (int nt = 0; nt < 8; nt++)
                    mma16816(acc[mt][nt], a[mt], b[nt]);
        }
        __syncthreads();   // protect buffers before next iteration's cp.async
    }

    // --- fused epilogue from register accumulators ---
    // c0,c1 -> row g=lane>>2, cols cb, cb+1 ; c2,c3 -> row g+8
    const int g = lane >> 2;
    const int cb0 = colBase + warp_n * 64 + (lane & 3) * 2;

    #pragma unroll
    for (int mt = 0; mt < 2; mt++) {
        const int r_lo = rowBase + warp_m * 32 + mt * 16 + g;
        const int r_hi = r_lo + 8;
        const int p_lo = (r_lo < BATCH) ? r_lo + BATCH : r_lo - BATCH;
        const int p_hi = (r_hi < BATCH) ? r_hi + BATCH : r_hi - BATCH;

        float sum_lo = 0.0f, sum_hi = 0.0f;
        #pragma unroll
        for (int nt = 0; nt < 8; nt++) {
            const int c0 = cb0 + nt * 8;
            const float s00 = acc[mt][nt][0];
            const float s01 = acc[mt][nt][1];
            const float s10 = acc[mt][nt][2];
            const float s11 = acc[mt][nt][3];
            if (c0 != r_lo)     sum_lo += fast_exp2s(s00);
            if (c0 + 1 != r_lo) sum_lo += fast_exp2s(s01);
            if (c0 != r_hi)     sum_hi += fast_exp2s(s10);
            if (c0 + 1 != r_hi) sum_hi += fast_exp2s(s11);
            if (c0 == p_lo)     g_pos[r_lo] = s00;
            if (c0 + 1 == p_lo) g_pos[r_lo] = s01;
            if (c0 == p_hi)     g_pos[r_hi] = s10;
            if (c0 + 1 == p_hi) g_pos[r_hi] = s11;
        }
        // reduce across the 4 lanes sharing these rows (lane%4 varies)
        #pragma unroll
        for (int o = 1; o < 4; o <<= 1) {
            sum_lo += __shfl_xor_sync(0xFFFFFFFFu, sum_lo, o);
            sum_hi += __shfl_xor_sync(0xFFFFFFFFu, sum_hi, o);
        }
        if ((lane & 3) == 0) {
            atomicAdd(&g_denom[r_lo], sum_lo);
            atomicAdd(&g_denom[r_hi], sum_hi);
        }
    }
}

// ---------------------------------------------------------------------------
// Kernel 3: loss_r = log(denom_r) - 2*pos_r; mean -> scalar
// ---------------------------------------------------------------------------
__global__ __launch_bounds__(256) void reduce_kernel(float* __restrict__ out) {
    __shared__ float s[256];
    float v = 0.0f;
    for (int i = threadIdx.x; i < NTOT; i += 256)
        v += logf(g_denom[i]) - 2.0f * g_pos[i];
    s[threadIdx.x] = v;
    __syncthreads();
    for (int stride = 128; stride > 0; stride >>= 1) {
        if (threadIdx.x < stride) s[threadIdx.x] += s[threadIdx.x + stride];
        __syncthreads();
    }
    if (threadIdx.x == 0) out[0] = s[0] * (1.0f / (float)NTOT);
}

// ---------------------------------------------------------------------------
extern "C" void kernel_launch(void* const* d_in, const int* in_sizes, int n_in,
                              void* d_out, int out_size) {
    const float* x_i = (const float*)d_in[0];
    const float* x_j = (const float*)d_in[1];
    float* out = (float*)d_out;

    cudaFuncSetAttribute(sim_kernel, cudaFuncAttributeMaxDynamicSharedMemorySize, SM_TOTAL);

    norm_kernel<<<NTOT, 128>>>(x_i, x_j);
    dim3 grid(NTOT / TILE, NTOT / TILE);   // (64, 64)
    sim_kernel<<<grid, 256, SM_TOTAL>>>();
    reduce_kernel<<<1, 256>>>(out);
}

// round 5
// speedup vs baseline: 28.6176x; 1.6765x over previous
#include <cuda_runtime.h>
#include <cuda_bf16.h>
#include <math.h>
#include <stdint.h>

// Problem constants
#define BATCH 4096
#define DIM   512
#define NTOT  8192
#define TILE  128
#define KCHUNK 64
#define NCHUNKS (DIM / KCHUNK)   // 8
#define NTILES  (NTOT / TILE)    // 64
#define NCTAS   (NTILES * (NTILES + 1) / 2)  // 2080 upper-tri tiles

// SMEM: double-buffered A and B tiles, each 128 rows x 64 bf16 = 16 KB
#define TILE_BYTES 16384
#define SM_A(buf) ((buf) * TILE_BYTES)
#define SM_B(buf) (2 * TILE_BYTES + (buf) * TILE_BYTES)
#define SM_TOTAL  (4 * TILE_BYTES)

// Scratch (no cudaMalloc allowed)
__device__ __nv_bfloat16 g_zb[NTOT * DIM];   // normalized Z, bf16 (8 MB)
__device__ float g_denom[NTOT];
__device__ float g_pos[NTOT];

// ---------------------------------------------------------------------------
__device__ __forceinline__ uint32_t smem_u32(const void* p) {
    uint32_t a;
    asm("{ .reg .u64 t; cvta.to.shared.u64 t, %1; cvt.u32.u64 %0, t; }" : "=r"(a) : "l"(p));
    return a;
}

__device__ __forceinline__ void cp_async16(uint32_t saddr, const void* gptr) {
    asm volatile("cp.async.cg.shared.global [%0], [%1], 16;" :: "r"(saddr), "l"(gptr));
}
__device__ __forceinline__ void cp_commit() {
    asm volatile("cp.async.commit_group;" ::: "memory");
}
template <int N>
__device__ __forceinline__ void cp_wait() {
    asm volatile("cp.async.wait_group %0;" :: "n"(N) : "memory");
}

__device__ __forceinline__ void ldsm_x4(uint32_t* r, uint32_t addr) {
    asm volatile("ldmatrix.sync.aligned.m8n8.x4.shared.b16 {%0,%1,%2,%3}, [%4];"
                 : "=r"(r[0]), "=r"(r[1]), "=r"(r[2]), "=r"(r[3]) : "r"(addr));
}

__device__ __forceinline__ void mma16816(float* c, const uint32_t* a, const uint32_t* b) {
    asm volatile(
        "mma.sync.aligned.m16n8k16.row.col.f32.bf16.bf16.f32 "
        "{%0,%1,%2,%3}, {%4,%5,%6,%7}, {%8,%9}, {%0,%1,%2,%3};"
        : "+f"(c[0]), "+f"(c[1]), "+f"(c[2]), "+f"(c[3])
        : "r"(a[0]), "r"(a[1]), "r"(a[2]), "r"(a[3]), "r"(b[0]), "r"(b[1]));
}

// Fast exp(2*s) on the FMA pipe (avoid MUFU.EX2 throughput wall).
__device__ __forceinline__ float fast_exp2s(float s) {
    float t = 2.8853900817779268f * s;      // 2 * log2(e)
    float fn = rintf(t);
    float f = t - fn;
    float p = fmaf(0.0013333558f, f, 0.0096181291f);
    p = fmaf(p, f, 0.0555041087f);
    p = fmaf(p, f, 0.2402265070f);
    p = fmaf(p, f, 0.6931471806f);
    p = fmaf(p, f, 1.0f);
    int n = (int)fn;
    float scale = __int_as_float((n + 127) << 23);
    return p * scale;
}

// ---------------------------------------------------------------------------
// Kernel 1: L2-normalize rows into bf16 Z; zero accumulators.
// ---------------------------------------------------------------------------
__global__ __launch_bounds__(128) void norm_kernel(const float* __restrict__ xi,
                                                   const float* __restrict__ xj) {
    const int row = blockIdx.x;
    const float* src = (row < BATCH) ? (xi + (size_t)row * DIM)
                                     : (xj + (size_t)(row - BATCH) * DIM);
    float4 v = ((const float4*)src)[threadIdx.x];
    float ss = v.x * v.x + v.y * v.y + v.z * v.z + v.w * v.w;
    #pragma unroll
    for (int o = 16; o > 0; o >>= 1) ss += __shfl_xor_sync(0xFFFFFFFFu, ss, o);
    __shared__ float ws[4];
    if ((threadIdx.x & 31) == 0) ws[threadIdx.x >> 5] = ss;
    __syncthreads();
    float tot = ws[0] + ws[1] + ws[2] + ws[3];
    float inv = 1.0f / fmaxf(sqrtf(tot), 1e-12f);

    __nv_bfloat162 h0 = __floats2bfloat162_rn(v.x * inv, v.y * inv);
    __nv_bfloat162 h1 = __floats2bfloat162_rn(v.z * inv, v.w * inv);
    uint2 u;
    u.x = *(uint32_t*)&h0;
    u.y = *(uint32_t*)&h1;
    ((uint2*)(g_zb + (size_t)row * DIM))[threadIdx.x] = u;

    if (threadIdx.x == 0) {
        g_denom[row] = 0.0f;
        g_pos[row] = 0.0f;
    }
}

// ---------------------------------------------------------------------------
// Kernel 2: symmetric-aware fused sim tiles. Only upper-triangular 128x128
// tiles (by <= bx) are computed; off-diagonal tiles feed BOTH row and column
// denominators (sim is symmetric). 1D grid of 2080 CTAs, triangular decode.
// ---------------------------------------------------------------------------
__global__ __launch_bounds__(256, 2) void sim_kernel() {
    extern __shared__ char smem[];
    const uint32_t sbase = smem_u32(smem);
    const int tid = threadIdx.x;
    const int wid = tid >> 5;
    const int lane = tid & 31;

    // triangular decode: off(i) = i*64 - i*(i-1)/2
    const int t = blockIdx.x;
    int by = (int)(64.5f - sqrtf(64.5f * 64.5f - 2.0f * (float)t));
    while ((by + 1) * NTILES - ((by + 1) * by) / 2 <= t) by++;
    while (by * NTILES - (by * (by - 1)) / 2 > t) by--;
    const int bx = by + (t - (by * NTILES - (by * (by - 1)) / 2));

    const int rowBase = by * TILE;
    const int colBase = bx * TILE;
    const bool diag = (by == bx);

    const int warp_m = wid & 3;     // 0..3 -> 32-row strip
    const int warp_n = wid >> 2;    // 0..1 -> 64-col strip

    const __nv_bfloat16* __restrict__ zb = g_zb;

    // --- cp.async load mapping: 1024 16B units per tile, 4 per thread ---
    uint32_t ld_soff[4];
    const __nv_bfloat16* ld_ga[4];
    const __nv_bfloat16* ld_gb[4];
    #pragma unroll
    for (int it = 0; it < 4; it++) {
        int idx = tid + it * 256;
        int r = idx >> 3;
        int c16 = idx & 7;
        ld_soff[it] = (uint32_t)(r * 128 + ((c16 * 16) ^ ((r & 7) << 4)));
        ld_ga[it] = zb + (size_t)(rowBase + r) * DIM + c16 * 8;
        ld_gb[it] = zb + (size_t)(colBase + r) * DIM + c16 * 8;
    }

    // --- ldmatrix address components (swizzle folded into col xor) ---
    uint32_t aRow[2], aMask[2];
    #pragma unroll
    for (int mt = 0; mt < 2; mt++) {
        int r = warp_m * 32 + mt * 16 + (lane & 15);
        aRow[mt] = (uint32_t)(r * 128);
        aMask[mt] = (uint32_t)((r & 7) << 4);
    }
    const uint32_t aColK = (uint32_t)((lane >> 4) * 16);

    uint32_t bRow[4], bMask[4];
    const int q = lane >> 3;
    #pragma unroll
    for (int p = 0; p < 4; p++) {
        int r = warp_n * 64 + (2 * p + (q >> 1)) * 8 + (lane & 7);
        bRow[p] = (uint32_t)(r * 128);
        bMask[p] = (uint32_t)((r & 7) << 4);
    }
    const uint32_t bColK = (uint32_t)((q & 1) * 16);

    float acc[2][8][4];
    #pragma unroll
    for (int mt = 0; mt < 2; mt++)
        #pragma unroll
        for (int nt = 0; nt < 8; nt++)
            #pragma unroll
            for (int k = 0; k < 4; k++) acc[mt][nt][k] = 0.0f;

    // --- prologue: chunk 0 -> buffer 0 ---
    #pragma unroll
    for (int it = 0; it < 4; it++) {
        cp_async16(sbase + SM_A(0) + ld_soff[it], ld_ga[it]);
        cp_async16(sbase + SM_B(0) + ld_soff[it], ld_gb[it]);
    }
    cp_commit();

    for (int kk = 0; kk < NCHUNKS; kk++) {
        const int buf = kk & 1;
        if (kk + 1 < NCHUNKS) {
            const int nb = (kk + 1) & 1;
            const int koff = (kk + 1) * KCHUNK;
            #pragma unroll
            for (int it = 0; it < 4; it++) {
                cp_async16(sbase + SM_A(nb) + ld_soff[it], ld_ga[it] + koff);
                cp_async16(sbase + SM_B(nb) + ld_soff[it], ld_gb[it] + koff);
            }
            cp_commit();
            cp_wait<1>();
        } else {
            cp_wait<0>();
        }
        __syncthreads();

        const uint32_t abase = sbase + SM_A(buf);
        const uint32_t bbase = sbase + SM_B(buf);

        #pragma unroll
        for (int kt = 0; kt < 4; kt++) {
            const uint32_t kb = (uint32_t)(kt * 32);
            uint32_t a[2][4];
            #pragma unroll
            for (int mt = 0; mt < 2; mt++)
                ldsm_x4(a[mt], abase + aRow[mt] + ((kb + aColK) ^ aMask[mt]));

            uint32_t b[8][2];
            #pragma unroll
            for (int p = 0; p < 4; p++) {
                uint32_t r4[4];
                ldsm_x4(r4, bbase + bRow[p] + ((kb + bColK) ^ bMask[p]));
                b[2 * p][0] = r4[0]; b[2 * p][1] = r4[1];
                b[2 * p + 1][0] = r4[2]; b[2 * p + 1][1] = r4[3];
            }

            #pragma unroll
            for (int mt = 0; mt < 2; mt++)
                #pragma unroll
                for (int nt = 0; nt < 8; nt++)
                    mma16816(acc[mt][nt], a[mt], b[nt]);
        }
        __syncthreads();
    }

    // --- fused epilogue ---
    // fragment map: c0,c1 -> row g=lane>>2, cols cb0, cb0+1 ; c2,c3 -> row g+8
    const int g = lane >> 2;
    const int cb0 = colBase + warp_n * 64 + (lane & 3) * 2;

    if (diag) {
        // rows == cols block: row sums only, exclude the exact diagonal.
        #pragma unroll
        for (int mt = 0; mt < 2; mt++) {
            const int r_lo = rowBase + warp_m * 32 + mt * 16 + g;
            const int r_hi = r_lo + 8;
            float sum_lo = 0.0f, sum_hi = 0.0f;
            #pragma unroll
            for (int nt = 0; nt < 8; nt++) {
                const int c0 = cb0 + nt * 8;
                if (c0 != r_lo)     sum_lo += fast_exp2s(acc[mt][nt][0]);
                if (c0 + 1 != r_lo) sum_lo += fast_exp2s(acc[mt][nt][1]);
                if (c0 != r_hi)     sum_hi += fast_exp2s(acc[mt][nt][2]);
                if (c0 + 1 != r_hi) sum_hi += fast_exp2s(acc[mt][nt][3]);
            }
            #pragma unroll
            for (int o = 1; o < 4; o <<= 1) {
                sum_lo += __shfl_xor_sync(0xFFFFFFFFu, sum_lo, o);
                sum_hi += __shfl_xor_sync(0xFFFFFFFFu, sum_hi, o);
            }
            if ((lane & 3) == 0) {
                atomicAdd(&g_denom[r_lo], sum_lo);
                atomicAdd(&g_denom[r_hi], sum_hi);
            }
        }
    } else {
        // off-diagonal: every exp feeds a row sum AND a column sum (symmetry).
        float csum[8][2];
        #pragma unroll
        for (int nt = 0; nt < 8; nt++) { csum[nt][0] = 0.0f; csum[nt][1] = 0.0f; }

        #pragma unroll
        for (int mt = 0; mt < 2; mt++) {
            const int r_lo = rowBase + warp_m * 32 + mt * 16 + g;
            const int r_hi = r_lo + 8;
            // rows here are < cols; partner in col range only if partner = r + B
            const int p_lo = r_lo + BATCH;
            const int p_hi = r_hi + BATCH;

            float sum_lo = 0.0f, sum_hi = 0.0f;
            #pragma unroll
            for (int nt = 0; nt < 8; nt++) {
                const int c0 = cb0 + nt * 8;
                const float s00 = acc[mt][nt][0];
                const float s01 = acc[mt][nt][1];
                const float s10 = acc[mt][nt][2];
                const float s11 = acc[mt][nt][3];
                const float e00 = fast_exp2s(s00);
                const float e01 = fast_exp2s(s01);
                const float e10 = fast_exp2s(s10);
                const float e11 = fast_exp2s(s11);
                sum_lo += e00 + e01;
                sum_hi += e10 + e11;
                csum[nt][0] += e00 + e10;
                csum[nt][1] += e01 + e11;
                // symmetric positive: sim[r, r+B] == sim[r+B, r]
                if (c0 == p_lo)     { g_pos[r_lo] = s00; g_pos[c0] = s00; }
                if (c0 + 1 == p_lo) { g_pos[r_lo] = s01; g_pos[c0 + 1] = s01; }
                if (c0 == p_hi)     { g_pos[r_hi] = s10; g_pos[c0] = s10; }
                if (c0 + 1 == p_hi) { g_pos[r_hi] = s11; g_pos[c0 + 1] = s11; }
            }
            #pragma unroll
            for (int o = 1; o < 4; o <<= 1) {
                sum_lo += __shfl_xor_sync(0xFFFFFFFFu, sum_lo, o);
                sum_hi += __shfl_xor_sync(0xFFFFFFFFu, sum_hi, o);
            }
            if ((lane & 3) == 0) {
                atomicAdd(&g_denom[r_lo], sum_lo);
                atomicAdd(&g_denom[r_hi], sum_hi);
            }
        }

        // column sums: reduce over the 8 row-groups (lanes differing in lane>>2)
        #pragma unroll
        for (int nt = 0; nt < 8; nt++) {
            float c0s = csum[nt][0];
            float c1s = csum[nt][1];
            #pragma unroll
            for (int o = 4; o < 32; o <<= 1) {
                c0s += __shfl_xor_sync(0xFFFFFFFFu, c0s, o);
                c1s += __shfl_xor_sync(0xFFFFFFFFu, c1s, o);
            }
            if (g == 0) {
                const int c0 = cb0 + nt * 8;
                atomicAdd(&g_denom[c0], c0s);
                atomicAdd(&g_denom[c0 + 1], c1s);
            }
        }
    }
}

// ---------------------------------------------------------------------------
// Kernel 3: loss_r = log(denom_r) - 2*pos_r; mean -> scalar
// ---------------------------------------------------------------------------
__global__ __launch_bounds__(1024) void reduce_kernel(float* __restrict__ out) {
    __shared__ float s[1024];
    float v = 0.0f;
    for (int i = threadIdx.x; i < NTOT; i += 1024)
        v += logf(g_denom[i]) - 2.0f * g_pos[i];
    s[threadIdx.x] = v;
    __syncthreads();
    for (int stride = 512; stride > 0; stride >>= 1) {
        if (threadIdx.x < stride) s[threadIdx.x] += s[threadIdx.x + stride];
        __syncthreads();
    }
    if (threadIdx.x == 0) out[0] = s[0] * (1.0f / (float)NTOT);
}

// ---------------------------------------------------------------------------
extern "C" void kernel_launch(void* const* d_in, const int* in_sizes, int n_in,
                              void* d_out, int out_size) {
    const float* x_i = (const float*)d_in[0];
    const float* x_j = (const float*)d_in[1];
    float* out = (float*)d_out;

    cudaFuncSetAttribute(sim_kernel, cudaFuncAttributeMaxDynamicSharedMemorySize, SM_TOTAL);

    norm_kernel<<<NTOT, 128>>>(x_i, x_j);
    sim_kernel<<<NCTAS, 256, SM_TOTAL>>>();
    reduce_kernel<<<1, 1024>>>(out);
}